// round 10
// baseline (speedup 1.0000x reference)
#include <cuda_runtime.h>
#include <cuda_bf16.h>
#include <cstdint>

// Problem constants (fixed by the dataset)
#define B_DIM   16
#define N_DIM   50000
#define E_DIM   1600000
#define BN      (B_DIM * N_DIM)
#define CLAMP_MIN_F (-10.0f)
#define CLAMP_MAX_F ( 10.0f)
#define EPS_F   (1e-6f)

// Transposed (N, B) scratch: each node's 16 batch values are contiguous (64B).
// 3 x 3.2MB = 9.6MB -> fully L2-resident.
__device__ float g_ET [N_DIM * B_DIM];   // E transposed
__device__ float g_OT [N_DIM * B_DIM];   // o_pre transposed
__device__ float g_ACC[N_DIM * B_DIM];   // gj_sum accumulator (memset to 0)

// ---------------------------------------------------------------------------
// Kernel A: transpose E and o_pre only (ACC is zeroed by a memset node; the
// E+chem term moved into the final kernel). q-split node-major: tid = q*N+n,
// coalesced input LDGs, 16B full-sector stores. 2/3 the volume of R9's prep.
// ---------------------------------------------------------------------------
__global__ void __launch_bounds__(256)
prep_kernel(const float* __restrict__ E,
            const float* __restrict__ o_pre)
{
    int tid = blockIdx.x * blockDim.x + threadIdx.x;
    if (tid >= 4 * N_DIM) return;
    int q = tid / N_DIM;          // 0..3 (batch quad)
    int n = tid - q * N_DIM;      // node

    float et[4], ot[4];
    #pragma unroll
    for (int j = 0; j < 4; j++) {
        int b = q * 4 + j;
        et[j] = __ldg(&E    [b * N_DIM + n]);
        ot[j] = __ldg(&o_pre[b * N_DIM + n]);
    }

    int t = n * B_DIM + q * 4;
    *reinterpret_cast<float4*>(&g_ET[t]) = make_float4(et[0], et[1], et[2], et[3]);
    *reinterpret_cast<float4*>(&g_OT[t]) = make_float4(ot[0], ot[1], ot[2], ot[3]);
}

// ---------------------------------------------------------------------------
// Kernel B: edge scatter (known-good; at the LTS roofline — untouched).
// 4 lanes per edge; each lane owns one batch quad (float4). Quad lanes load
// contiguous 16B pieces of the edge's 64B block (one 64B request per quad).
// red.global.add.v4.f32 -> no-return L2-side add, one RED.128 per lane.
// ---------------------------------------------------------------------------
__global__ void __launch_bounds__(256)
edge_kernel(const float* __restrict__ w,
            const int*   __restrict__ src,
            const int*   __restrict__ dst)
{
    int t = blockIdx.x * blockDim.x + threadIdx.x;
    if (t >= E_DIM * 4) return;
    int e = t >> 2;
    int q = t & 3;

    int   s  = __ldg(&src[e]);
    int   d  = __ldg(&dst[e]);
    float wv = __ldg(&w[e]);

    const float4 Oj = __ldg(reinterpret_cast<const float4*>(&g_OT[s * B_DIM + q * 4]));
    const float4 En = __ldg(reinterpret_cast<const float4*>(&g_ET[d * B_DIM + q * 4]));

    float4 c;
    c.x = (Oj.x >= En.x) ? (Oj.x * wv) : (-Oj.x * wv);
    c.y = (Oj.y >= En.y) ? (Oj.y * wv) : (-Oj.y * wv);
    c.z = (Oj.z >= En.z) ? (Oj.z * wv) : (-Oj.z * wv);
    c.w = (Oj.w >= En.w) ? (Oj.w * wv) : (-Oj.w * wv);

    float* p = &g_ACC[d * B_DIM + q * 4];
    asm volatile("red.global.add.v4.f32 [%0], {%1, %2, %3, %4};"
                 :: "l"(p), "f"(c.x), "f"(c.y), "f"(c.z), "f"(c.w)
                 : "memory");
}

// ---------------------------------------------------------------------------
// Kernel C: epilogue, smem-staged both ways, now also absorbing chem.
// Phase A (q-split): dense chem loads -> smem.
// Phase B (node-quad): dense 64B/node loads of ACC(gj_sum) and ET; S =
//   clip(E + chem + gj_sum); outputs staged to smem.
// Phase C (q-split): dense stores of both output planes.
// ---------------------------------------------------------------------------
__global__ void __launch_bounds__(256)
final_kernel(const float* __restrict__ chem,
             const float* __restrict__ threshold,
             const float* __restrict__ decay,
             float* __restrict__ out)
{
    __shared__ float s_c [B_DIM][65];
    __shared__ float s_no[B_DIM][65];
    __shared__ float s_ne[B_DIM][65];

    const int n0 = blockIdx.x * 64;
    const int t  = threadIdx.x;

    // Phase A: dense chem loads (q-split within the block).
    {
        int q  = t >> 6;          // 0..3
        int nl = t & 63;          // 0..63
        int n  = n0 + nl;
        if (n < N_DIM) {
            #pragma unroll
            for (int j = 0; j < 4; j++) {
                int b = q * 4 + j;
                s_c[b][nl] = __ldg(&chem[b * N_DIM + n]);
            }
        }
    }
    __syncthreads();

    // Phase B: dense ACC/ET loads + epilogue math.
    {
        int ni = t >> 2;          // local node
        int qq = t & 3;           // batch quad
        int n  = n0 + ni;
        if (n < N_DIM) {
            int base = n * B_DIM + qq * 4;
            float4 Gv = *reinterpret_cast<const float4*>(&g_ACC[base]);  // gj_sum
            float4 Ev = *reinterpret_cast<const float4*>(&g_ET [base]);
            float thr = __ldg(&threshold[n]);   // broadcast across the quad
            float dec = __ldg(&decay[n]);

            float Ga[4] = {Gv.x, Gv.y, Gv.z, Gv.w};
            float Ea[4] = {Ev.x, Ev.y, Ev.z, Ev.w};
            #pragma unroll
            for (int j = 0; j < 4; j++) {
                int b = qq * 4 + j;
                float ev = Ea[j];
                float S  = ev + s_c[b][ni] + Ga[j];
                S = fminf(fmaxf(S, CLAMP_MIN_F), CLAMP_MAX_F);
                bool  gt    = S > thr;
                float new_o = fmaxf(S - thr, 0.0f);
                bool  mask  = (!gt) && (fabsf(S - ev) <= EPS_F);
                float new_e = gt ? new_o : (mask ? (ev - dec) : S);
                s_no[b][ni] = new_o;
                s_ne[b][ni] = new_e;
            }
        }
    }
    __syncthreads();

    // Phase C: dense stores (q-split).
    {
        int q  = t >> 6;
        int nl = t & 63;
        int n  = n0 + nl;
        if (n < N_DIM) {
            #pragma unroll
            for (int j = 0; j < 4; j++) {
                int b = q * 4 + j;
                out[b * N_DIM + n]      = s_no[b][nl];
                out[BN + b * N_DIM + n] = s_ne[b][nl];
            }
        }
    }
}

// ---------------------------------------------------------------------------
// Launch. Inputs (metadata order):
//   0 chem_influence (B,N) f32   1 E (B,N) f32       2 o_pre (B,N) f32
//   3 w (E,) f32                 4 threshold (N,) f32 5 decay (N,) f32
//   6 src (E,) i32               7 dst (E,) i32
// Output: new_o (B,N) then new_e (B,N) concatenated, f32.
// ---------------------------------------------------------------------------
extern "C" void kernel_launch(void* const* d_in, const int* in_sizes, int n_in,
                              void* d_out, int out_size)
{
    const float* chem  = (const float*)d_in[0];
    const float* E     = (const float*)d_in[1];
    const float* o_pre = (const float*)d_in[2];
    const float* w     = (const float*)d_in[3];
    const float* thr   = (const float*)d_in[4];
    const float* dec   = (const float*)d_in[5];
    const int*   src   = (const int*)  d_in[6];
    const int*   dst   = (const int*)  d_in[7];
    float* out = (float*)d_out;

    // Zero gj_sum accumulator (memset node; graph-capturable, no allocation).
    void* acc_ptr = nullptr;
    cudaGetSymbolAddress(&acc_ptr, g_ACC);
    cudaMemsetAsync(acc_ptr, 0, (size_t)N_DIM * B_DIM * sizeof(float));

    const int THREADS = 256;
    int qn_blocks   = (4 * N_DIM + THREADS - 1) / THREADS;      // 782
    int node_blocks = (N_DIM + 63) / 64;                        // 782
    int edge_blocks = (E_DIM * 4 + THREADS - 1) / THREADS;      // 25000

    prep_kernel <<<qn_blocks,   THREADS>>>(E, o_pre);
    edge_kernel <<<edge_blocks, THREADS>>>(w, src, dst);
    final_kernel<<<node_blocks, THREADS>>>(chem, thr, dec, out);
}

// round 11
// speedup vs baseline: 1.0520x; 1.0520x over previous
#include <cuda_runtime.h>
#include <cuda_bf16.h>
#include <cstdint>

// Problem constants (fixed by the dataset)
#define B_DIM   16
#define N_DIM   50000          // divisible by 4
#define E_DIM   1600000
#define BN      (B_DIM * N_DIM)
#define CLAMP_MIN_F (-10.0f)
#define CLAMP_MAX_F ( 10.0f)
#define EPS_F   (1e-6f)

// Transposed (N, B) scratch: each node's 16 batch values are contiguous (64B).
// 3 x 3.2MB = 9.6MB -> fully L2-resident.
__device__ float g_ET [N_DIM * B_DIM];   // E transposed
__device__ float g_OT [N_DIM * B_DIM];   // o_pre transposed
__device__ float g_ACC[N_DIM * B_DIM];   // accumulator, init to E + chem

// ---------------------------------------------------------------------------
// Kernel A: transpose + init accumulator; smem-staged, fully vectorized.
// Block = 64 nodes.
// Phase 1: t -> (b = t>>4, n4 = t&15): 3 dense float4 LDG per thread
//   (per b-row a warp covers 256B contiguous). Stage to smem.
// Phase 2: t -> (ni = t>>2, qq = t&3): 3 dense float4 STG per thread
//   (4 lanes emit one node's contiguous 64B; warp stores 512B runs).
// 6 vector mem-ops/thread vs R9's 15 mostly-scalar ones.
// ---------------------------------------------------------------------------
__global__ void __launch_bounds__(256)
prep_kernel(const float* __restrict__ chem,
            const float* __restrict__ E,
            const float* __restrict__ o_pre)
{
    __shared__ float4 s_e[B_DIM][17];   // rows padded: 17 float4 = 68 floats
    __shared__ float4 s_o[B_DIM][17];
    __shared__ float4 s_a[B_DIM][17];

    const int n0 = blockIdx.x * 64;
    const int t  = threadIdx.x;

    // Phase 1: dense float4 loads (b-major within the block).
    {
        int b  = t >> 4;           // 0..15
        int n4 = t & 15;           // 0..15 (node quad within block)
        int n  = n0 + n4 * 4;
        if (n < N_DIM) {           // N % 4 == 0 -> quads never split
            float4 e = __ldg(reinterpret_cast<const float4*>(&E    [b * N_DIM + n]));
            float4 o = __ldg(reinterpret_cast<const float4*>(&o_pre[b * N_DIM + n]));
            float4 c = __ldg(reinterpret_cast<const float4*>(&chem [b * N_DIM + n]));
            s_e[b][n4] = e;
            s_o[b][n4] = o;
            s_a[b][n4] = make_float4(e.x + c.x, e.y + c.y, e.z + c.z, e.w + c.w);
        }
    }
    __syncthreads();

    // Phase 2: dense float4 stores (node-major).
    {
        int ni = t >> 2;           // 0..63 local node
        int qq = t & 3;            // batch quad
        int n  = n0 + ni;
        if (n < N_DIM) {
            const float* ef = reinterpret_cast<const float*>(s_e);
            const float* of = reinterpret_cast<const float*>(s_o);
            const float* af = reinterpret_cast<const float*>(s_a);
            int b0 = qq * 4;
            // scalar smem view: row b has 68 floats; element ni of row b.
            float4 ve = make_float4(ef[(b0+0)*68 + ni], ef[(b0+1)*68 + ni],
                                    ef[(b0+2)*68 + ni], ef[(b0+3)*68 + ni]);
            float4 vo = make_float4(of[(b0+0)*68 + ni], of[(b0+1)*68 + ni],
                                    of[(b0+2)*68 + ni], of[(b0+3)*68 + ni]);
            float4 va = make_float4(af[(b0+0)*68 + ni], af[(b0+1)*68 + ni],
                                    af[(b0+2)*68 + ni], af[(b0+3)*68 + ni]);
            int base = n * B_DIM + b0;
            *reinterpret_cast<float4*>(&g_ET [base]) = ve;
            *reinterpret_cast<float4*>(&g_OT [base]) = vo;
            *reinterpret_cast<float4*>(&g_ACC[base]) = va;
        }
    }
}

// ---------------------------------------------------------------------------
// Kernel B: edge scatter (known-good; ~91% of LTS cap — untouched).
// 4 lanes per edge; each lane owns one batch quad (float4). Quad lanes load
// contiguous 16B pieces of the edge's 64B block (one 64B request per quad).
// red.global.add.v4.f32 -> no-return L2-side add, one RED.128 per lane.
// ---------------------------------------------------------------------------
__global__ void __launch_bounds__(256)
edge_kernel(const float* __restrict__ w,
            const int*   __restrict__ src,
            const int*   __restrict__ dst)
{
    int t = blockIdx.x * blockDim.x + threadIdx.x;
    if (t >= E_DIM * 4) return;
    int e = t >> 2;
    int q = t & 3;

    int   s  = __ldg(&src[e]);
    int   d  = __ldg(&dst[e]);
    float wv = __ldg(&w[e]);

    const float4 Oj = __ldg(reinterpret_cast<const float4*>(&g_OT[s * B_DIM + q * 4]));
    const float4 En = __ldg(reinterpret_cast<const float4*>(&g_ET[d * B_DIM + q * 4]));

    float4 c;
    c.x = (Oj.x >= En.x) ? (Oj.x * wv) : (-Oj.x * wv);
    c.y = (Oj.y >= En.y) ? (Oj.y * wv) : (-Oj.y * wv);
    c.z = (Oj.z >= En.z) ? (Oj.z * wv) : (-Oj.z * wv);
    c.w = (Oj.w >= En.w) ? (Oj.w * wv) : (-Oj.w * wv);

    float* p = &g_ACC[d * B_DIM + q * 4];
    asm volatile("red.global.add.v4.f32 [%0], {%1, %2, %3, %4};"
                 :: "l"(p), "f"(c.x), "f"(c.y), "f"(c.z), "f"(c.w)
                 : "memory");
}

// ---------------------------------------------------------------------------
// Kernel C: epilogue; smem-staged, vectorized stores. Block = 64 nodes.
// Phase 1: t -> (ni, qq): dense float4 loads of ACC (= E+chem+gj_sum, L2 hit)
//   and ET; epilogue math; stage results (scalar smem writes).
// Phase 2: t -> (b, n4): 2 dense float4 STG per thread (out planes).
// ---------------------------------------------------------------------------
__global__ void __launch_bounds__(256)
final_kernel(const float* __restrict__ threshold,
             const float* __restrict__ decay,
             float* __restrict__ out)
{
    __shared__ float4 s_no[B_DIM][17];
    __shared__ float4 s_ne[B_DIM][17];

    const int n0 = blockIdx.x * 64;
    const int t  = threadIdx.x;

    // Phase 1: dense loads + epilogue math.
    {
        int ni = t >> 2;
        int qq = t & 3;
        int n  = n0 + ni;
        if (n < N_DIM) {
            int base = n * B_DIM + qq * 4;
            float4 Sv = *reinterpret_cast<const float4*>(&g_ACC[base]);
            float4 Ev = *reinterpret_cast<const float4*>(&g_ET [base]);
            float thr = __ldg(&threshold[n]);   // broadcast across the quad
            float dec = __ldg(&decay[n]);

            float* nof = reinterpret_cast<float*>(s_no);
            float* nef = reinterpret_cast<float*>(s_ne);
            float Sa[4] = {Sv.x, Sv.y, Sv.z, Sv.w};
            float Ea[4] = {Ev.x, Ev.y, Ev.z, Ev.w};
            #pragma unroll
            for (int j = 0; j < 4; j++) {
                int b = qq * 4 + j;
                float S  = fminf(fmaxf(Sa[j], CLAMP_MIN_F), CLAMP_MAX_F);
                float ev = Ea[j];
                bool  gt    = S > thr;
                float new_o = fmaxf(S - thr, 0.0f);
                bool  mask  = (!gt) && (fabsf(S - ev) <= EPS_F);
                float new_e = gt ? new_o : (mask ? (ev - dec) : S);
                nof[b * 68 + ni] = new_o;
                nef[b * 68 + ni] = new_e;
            }
        }
    }
    __syncthreads();

    // Phase 2: dense float4 stores (b-major).
    {
        int b  = t >> 4;           // 0..15
        int n4 = t & 15;           // node quad
        int n  = n0 + n4 * 4;
        if (n < N_DIM) {
            *reinterpret_cast<float4*>(&out[b * N_DIM + n])      = s_no[b][n4];
            *reinterpret_cast<float4*>(&out[BN + b * N_DIM + n]) = s_ne[b][n4];
        }
    }
}

// ---------------------------------------------------------------------------
// Launch. Inputs (metadata order):
//   0 chem_influence (B,N) f32   1 E (B,N) f32       2 o_pre (B,N) f32
//   3 w (E,) f32                 4 threshold (N,) f32 5 decay (N,) f32
//   6 src (E,) i32               7 dst (E,) i32
// Output: new_o (B,N) then new_e (B,N) concatenated, f32.
// ---------------------------------------------------------------------------
extern "C" void kernel_launch(void* const* d_in, const int* in_sizes, int n_in,
                              void* d_out, int out_size)
{
    const float* chem  = (const float*)d_in[0];
    const float* E     = (const float*)d_in[1];
    const float* o_pre = (const float*)d_in[2];
    const float* w     = (const float*)d_in[3];
    const float* thr   = (const float*)d_in[4];
    const float* dec   = (const float*)d_in[5];
    const int*   src   = (const int*)  d_in[6];
    const int*   dst   = (const int*)  d_in[7];
    float* out = (float*)d_out;

    const int THREADS = 256;
    int node_blocks = (N_DIM + 63) / 64;                        // 782
    int edge_blocks = (E_DIM * 4 + THREADS - 1) / THREADS;      // 25000

    prep_kernel <<<node_blocks, THREADS>>>(chem, E, o_pre);
    edge_kernel <<<edge_blocks, THREADS>>>(w, src, dst);
    final_kernel<<<node_blocks, THREADS>>>(thr, dec, out);
}